// round 15
// baseline (speedup 1.0000x reference)
#include <cuda_runtime.h>

#define M_TOTAL 8192
#define NPT 128
#define NTILES 64
#define RESULT_ELEMS (M_TOTAL * 7)   // 57344
#define THREADS 1024

__device__ unsigned int g_keys32[M_TOTAL];
__device__ unsigned int g_keyslo[M_TOTAL];
__device__ unsigned int g_validcnt[NTILES];
__device__ unsigned long long g_bar = 0;

extern __shared__ unsigned int sk32[];   // 8192 uint = 32KB

__global__ void __launch_bounds__(THREADS) fused_nms_kernel(const float* __restrict__ tr,
                                                            const int* __restrict__ tp,
                                                            float* __restrict__ out,
                                                            int writeKeep) {
    const int tile = blockIdx.x;
    const int tid = threadIdx.x;

    __shared__ float s_in[NPT * 7];
    __shared__ unsigned long long s_keyraw[NPT];
    __shared__ float4 s_sbox[NPT];
    __shared__ unsigned int s_klo[NPT];
    __shared__ unsigned int s_validmask[4];
    __shared__ unsigned int s_wvc[4];
    __shared__ unsigned int s_rownz[4];
    __shared__ uint4 s_sup[NPT];
    __shared__ float s_rec[NPT][8];
    __shared__ unsigned int s_kw[4];
    __shared__ int s_grank[NPT];
    __shared__ unsigned int s_vc[NTILES];
    __shared__ unsigned long long s_target;

    // =====================================================================
    // Pre-publish parallel region.
    //   warps 0-3   (  0-127): keys -> sort -> publish (fast path)
    //   warps 4-7   (128-255): wait bar3 -> rank + transform + record scatter
    //   warps 8-14  (256-479): stage s_in, arrive bar3
    //   warps 15-31 (480-1023): zero s_sup/rownz/grank
    // barrier 3 count = 128 (w0-3 arrive) + 128 (w4-7 sync) + 224 (w8-14 arrive) = 480
    // =====================================================================
    if (tid < 128) {
        if (tid < 4) s_validmask[tid] = 0;
        const int g = tile * NPT + tid;
        const float score = tr[(size_t)g * 7 + 4];   // scalar score load only
        const int valid = (score > 0.05f) ? 1 : 0;
        const float skey = valid ? score : __fsub_rn(score, 1e9f);
        unsigned int ob = __float_as_uint(skey);
        ob = (ob & 0x80000000u) ? ~ob : (ob | 0x80000000u);
        const unsigned long long mykey =
            ((unsigned long long)ob << 32) | (unsigned int)(~(unsigned int)g);
        s_keyraw[tid] = mykey;
        const unsigned int bal = __ballot_sync(0xFFFFFFFFu, valid);
        if ((tid & 31) == 0) s_wvc[tid >> 5] = __popc(bal);

        asm volatile("bar.arrive 3, 480;" ::: "memory");   // keys visible to w4-7
        asm volatile("bar.sync 1, 128;" ::: "memory");     // keys visible within w0-3

        int rank = 0;
        #pragma unroll 16
        for (int j = 0; j < NPT; j++) rank += (s_keyraw[j] > mykey) ? 1 : 0;

        const unsigned int khi = (unsigned int)(mykey >> 32);
        g_keys32[tile * NPT + rank] = khi;
        g_keyslo[tile * NPT + rank] = (unsigned int)mykey;
        sk32[(tile << 7) + rank] = khi;
        s_klo[rank] = (unsigned int)mykey;
        atomicOr(&s_validmask[rank >> 5], (unsigned int)valid << (rank & 31));

        asm volatile("bar.sync 1, 128;" ::: "memory");     // key STGs done

        if (tid == 0) {
            g_validcnt[tile] = s_wvc[0] + s_wvc[1] + s_wvc[2] + s_wvc[3];
            unsigned long long ticket;
            asm volatile("atom.release.gpu.add.u64 %0, [%1], %2;"
                         : "=l"(ticket) : "l"(&g_bar), "l"(1ULL) : "memory");
            s_target = (ticket / NTILES + 1ULL) * NTILES;
        }
    } else if (tid < 256) {
        // ---- transform worker: element e = tid-128 ----
        const int e = tid - 128;
        asm volatile("bar.sync 3, 480;" ::: "memory");     // wait keys + s_in

        const unsigned long long ke = s_keyraw[e];
        int rank = 0;
        #pragma unroll 16
        for (int j = 0; j < NPT; j++) rank += (s_keyraw[j] > ke) ? 1 : 0;

        const float* r = s_in + e * 7;
        float b0 = r[0], b1 = r[1], b2 = r[2], b3 = r[3];
        const float score = r[4], labelf = r[5], growth = r[6];
        const float hs = (float)tp[tile * 4 + 0];
        const float ws = (float)tp[tile * 4 + 2];
        b0 = fminf(fmaxf(__fadd_rn(b0, ws), 0.0f), 4096.0f);
        b1 = fminf(fmaxf(__fadd_rn(b1, hs), 0.0f), 4096.0f);
        b2 = fminf(fmaxf(__fadd_rn(b2, ws), 0.0f), 4096.0f);
        b3 = fminf(fmaxf(__fadd_rn(b3, hs), 0.0f), 4096.0f);

        const float shift = __fmul_rn(labelf, 8192.0f);
        const float x0  = __fadd_rn(b0, shift);
        const float x1c = __fadd_rn(b1, shift);
        const float x2  = __fadd_rn(b2, shift);
        const float x3  = __fadd_rn(b3, shift);

        s_sbox[rank] = make_float4(x0, x1c, x2, x3);
        s_rec[rank][0] = b0; s_rec[rank][1] = b1;
        s_rec[rank][2] = b2; s_rec[rank][3] = b3;
        s_rec[rank][4] = score; s_rec[rank][5] = labelf; s_rec[rank][6] = growth;
    } else if (tid < 480) {
        // ---- stage s_in (224 float4), then arrive ----
        const float4* src = (const float4*)(tr + (size_t)tile * NPT * 7);
        ((float4*)s_in)[tid - 256] = src[tid - 256];
        asm volatile("bar.arrive 3, 480;" ::: "memory");
    } else {
        // ---- zero helpers ----
        if (tid < 992) ((unsigned int*)s_sup)[tid - 480] = 0;
        else if (tid < 996) s_rownz[tid - 992] = 0;
        if (tid >= 480 && tid < 608) s_grank[tid - 480] = 0;
    }
    __syncthreads();

    // ---- suppression matrix; (row i, 16-col group w), warp-uniform j ----
    {
        const int i = tid & 127;
        const int w = tid >> 7;
        unsigned int half16 = 0;
        if (i < ((w + 1) << 4)) {
            const float4 bi = s_sbox[i];
            const float ai = __fmul_rn(__fsub_rn(bi.z, bi.x), __fsub_rn(bi.w, bi.y));
            #pragma unroll 4
            for (int jj = 0; jj < 16; jj++) {
                const int j = (w << 4) + jj;          // uniform -> broadcast LDS
                const float4 bj = s_sbox[j];
                const float ltx = fmaxf(bi.x, bj.x), lty = fmaxf(bi.y, bj.y);
                const float rbx = fminf(bi.z, bj.z), rby = fminf(bi.w, bj.w);
                const float wx = fmaxf(__fsub_rn(rbx, ltx), 0.0f);
                const float wy = fmaxf(__fsub_rn(rby, lty), 0.0f);
                // inter==0 -> iou==0 exactly (union>0): never suppresses.
                if ((j > i) && (wx > 0.0f) && (wy > 0.0f)) {
                    const float aj = __fmul_rn(__fsub_rn(bj.z, bj.x),
                                               __fsub_rn(bj.w, bj.y));
                    const float inter = __fmul_rn(wx, wy);
                    const float uni = __fsub_rn(__fadd_rn(ai, aj), inter);
                    const float iou = __fdiv_rn(inter, __fadd_rn(uni, 1e-8f));
                    if (iou > 0.5f) half16 |= (1u << jj);
                }
            }
        }
        if (half16)
            atomicOr(&((unsigned int*)&s_sup[i])[w >> 1], half16 << ((w & 1) * 16));
        const unsigned int nz = __ballot_sync(0xFFFFFFFFu, half16 != 0);
        if ((tid & 31) == 0 && nz) atomicOr(&s_rownz[(tid >> 5) & 3], nz);
    }
    __syncthreads();

    // ---- sparse greedy reduce (single thread; overlaps barrier wait) + poll ----
    if (tid == 0) {
        unsigned int kw[4];
        kw[0] = s_validmask[0]; kw[1] = s_validmask[1];
        kw[2] = s_validmask[2]; kw[3] = s_validmask[3];
        #pragma unroll
        for (int w = 0; w < 4; w++) {
            const unsigned int rz = s_rownz[w];
            unsigned int act = kw[w] & rz;
            while (act) {
                const int ib = __ffs(act) - 1;
                const uint4 s = s_sup[w * 32 + ib];
                kw[0] &= ~s.x; kw[1] &= ~s.y; kw[2] &= ~s.z; kw[3] &= ~s.w;
                act = kw[w] & rz & (0xFFFFFFFEu << ib);
            }
        }
        s_kw[0] = kw[0]; s_kw[1] = kw[1]; s_kw[2] = kw[2]; s_kw[3] = kw[3];

        const unsigned long long target = s_target;
        unsigned long long cur;
        do {
            asm volatile("ld.acquire.gpu.u64 %0, [%1];"
                         : "=l"(cur) : "l"(&g_bar) : "memory");
        } while (cur < target);
    }
    __syncthreads();

    // ---- stage hi-keys (32KB) + valid counts ----
    {
        const uint4* src = (const uint4*)g_keys32;
        uint4* dst = (uint4*)sk32;
        #pragma unroll
        for (int idx = tid; idx < M_TOTAL / 4; idx += THREADS) dst[idx] = __ldcg(src + idx);
    }
    if (tid < NTILES) s_vc[tid] = __ldcg(g_validcnt + tid);
    __syncthreads();

    // ---- rank: valid -> 8-state interleaved searches; invalid -> arithmetic ----
    {
        const int e_local = tid & 127;
        const int grp = tid >> 7;
        const unsigned int k32 = sk32[(tile << 7) + e_local];

        if (k32 & 0x80000000u) {
            const unsigned int klo = s_klo[e_local];
            const unsigned int* base = sk32 + (grp << 10);
            int lo[8];
            #pragma unroll
            for (int t = 0; t < 8; t++) lo[t] = 0;
            #pragma unroll
            for (int half = 64; half >= 1; half >>= 1) {
                #pragma unroll
                for (int t = 0; t < 8; t++) {
                    if (base[(t << 7) + lo[t] + half - 1] > k32) lo[t] += half;
                }
            }
            int partial = 0;
            #pragma unroll
            for (int t = 0; t < 8; t++) {
                int j = lo[t];
                partial += j;
                const int tb = (grp << 10) + (t << 7);
                while (j < NPT && sk32[tb + j] == k32) {
                    partial += (__ldcg(g_keyslo + tb + j) > klo) ? 1 : 0;
                    j++;
                }
            }
            if (partial) atomicAdd(&s_grank[e_local], partial);
        } else if (grp == 0) {
            int totValid = 0, invBefore = 0;
            #pragma unroll 8
            for (int t = 0; t < NTILES; t++) {
                const int v = (int)s_vc[t];
                totValid += v;
                if (t < tile) invBefore += NPT - v;
            }
            s_grank[e_local] = totValid + invBefore + (e_local - (int)s_vc[tile]);
        }
    }
    __syncthreads();

    // ---- fully parallel scatter ----
    if (tid < 896) {
        const int e = tid / 7;
        const int c = tid - e * 7;
        const int rank = s_grank[e];
        const unsigned int kbit = (s_kw[e >> 5] >> (e & 31)) & 1u;
        const float keepf = kbit ? 1.0f : 0.0f;
        out[(size_t)rank * 7 + c] = s_rec[e][c] * keepf;
    } else if (writeKeep) {
        const int e = tid - 896;
        const int rank = s_grank[e];
        const unsigned int kbit = (s_kw[e >> 5] >> (e & 31)) & 1u;
        out[RESULT_ELEMS + rank] = kbit ? 1.0f : 0.0f;
    }
}

__global__ void fill_zero_kernel(float* __restrict__ out, int start, int end) {
    int i = start + blockIdx.x * blockDim.x + threadIdx.x;
    if (i < end) out[i] = 0.0f;
}

extern "C" void kernel_launch(void* const* d_in, const int* in_sizes, int n_in,
                              void* d_out, int out_size) {
    const float* tr = (const float*)d_in[0];
    const int*   tp = (const int*)d_in[1];
    float* out = (float*)d_out;

    const int writeKeep = (out_size >= RESULT_ELEMS + M_TOTAL) ? 1 : 0;
    const int covered = writeKeep ? (RESULT_ELEMS + M_TOTAL) : RESULT_ELEMS;
    if (out_size > covered) {
        const int tail = out_size - covered;
        fill_zero_kernel<<<(tail + 255) / 256, 256>>>(out, covered, out_size);
    }

    fused_nms_kernel<<<NTILES, THREADS, M_TOTAL * sizeof(unsigned int)>>>(
        tr, tp, out, writeKeep);
}